// round 12
// baseline (speedup 1.0000x reference)
#include <cuda_runtime.h>
#include <cuda_bf16.h>
#include <math.h>
#include <stdint.h>

#define NMAT 4
#define NSUB 4096
#define DIM 64
#define KTOP 20
#define NROWS 8192
#define DELTA 0.008f
#define FULLM 0xffffffffu
#define CAND 48            // candidates per quarter-row

// device global scratch (no allocation allowed)
__device__ float g_v1[NMAT][NSUB][DIM];
__device__ float g_v2[NMAT][NSUB][DIM];
__device__ __nv_bfloat16 g_v1b[NMAT][NSUB][DIM];
__device__ __nv_bfloat16 g_v2b[NMAT][NSUB][DIM];
__device__ float          g_cm[NROWS][256];       // per-row 32-col sub-chunk maxima
__device__ float          g_T[NROWS];             // per-row filter threshold
__device__ float          g_cval[NROWS][4 * CAND];
__device__ unsigned short g_ccol[NROWS][4 * CAND];

__device__ __forceinline__ uint32_t smem_u32(const void* p) {
    uint32_t a;
    asm("{ .reg .u64 t; cvta.to.shared.u64 t, %1; cvt.u32.u64 %0, t; }" : "=r"(a) : "l"(p));
    return a;
}

// ---------------------------------------------------------------------------
// v = emb @ w + b (fp32) + bf16 copy
// ---------------------------------------------------------------------------
__global__ void compute_v_kernel(const float* __restrict__ emb1,
                                 const float* __restrict__ emb2,
                                 const float* __restrict__ w1,
                                 const float* __restrict__ w2,
                                 const float* __restrict__ b1,
                                 const float* __restrict__ b2) {
    int which = blockIdx.z;
    int k = blockIdx.y;
    int tile = blockIdx.x;
    const float* emb = which ? emb2 : emb1;
    const float* w   = which ? w2   : w1;
    const float* b   = which ? b2   : b1;
    float* vout            = which ? &g_v2[0][0][0]  : &g_v1[0][0][0];
    __nv_bfloat16* voutb   = which ? &g_v2b[0][0][0] : &g_v1b[0][0][0];

    __shared__ float semb[64 * 65];
    __shared__ float sw[64 * 64];
    __shared__ float sb[64];

    int tid = threadIdx.x;
    for (int t = tid; t < 4096; t += 256) {
        int r = t >> 6, e = t & 63;
        semb[r * 65 + e] = emb[(size_t)(k * NSUB + tile * 64 + r) * 64 + e];
        sw[t] = w[k * 4096 + t];
    }
    if (tid < 64) sb[tid] = b[k * 64 + tid];
    __syncthreads();

    int nl = tid & 63, q = tid >> 6;
    float acc[16];
#pragma unroll
    for (int d = 0; d < 16; d++) acc[d] = 0.f;

#pragma unroll 4
    for (int e = 0; e < 64; e++) {
        float a = semb[nl * 65 + e];
#pragma unroll
        for (int jj = 0; jj < 4; jj++) {
            float4 wv = *(const float4*)&sw[e * 64 + q * 16 + jj * 4];
            acc[jj * 4 + 0] += a * wv.x;
            acc[jj * 4 + 1] += a * wv.y;
            acc[jj * 4 + 2] += a * wv.z;
            acc[jj * 4 + 3] += a * wv.w;
        }
    }

    size_t rowoff = (size_t)(k * NSUB + tile * 64 + nl) * 64;
    float* orow = vout + rowoff;
    __nv_bfloat16* orowb = voutb + rowoff;
#pragma unroll
    for (int dd = 0; dd < 16; dd++) {
        int d = q * 16 + dd;
        float v = acc[dd] + sb[d];
        orow[d]  = v;
        orowb[d] = __float2bfloat16(v);
    }
}

// ---------------------------------------------------------------------------
// HMMA plumbing. 256 threads, 64-row x 2048-col tile (32 chunks of 64 cols).
// warp w = (rowband rb = w&3) x (colhalf ch = w>>2); warp does 16 rows x 32 cols.
// B: 4-stage cp.async ring, 3-deep prefetch. B frags via ldmatrix.x4.
// grid = (xq: 4 [colmodule j = xq>>1, quarter qq = xq&1], rowtile: 128).
// ---------------------------------------------------------------------------
#define OFF_A  0
#define OFF_B  9216
#define SM_AB  46080            // A(9216) + 4 B stages (4x9216)

#define MMA_CHUNK4(acc, af, bbuf, ch, lane)                                     \
    do {                                                                        \
        uint32_t baddr0 = (bbuf) + ((ch) * 32 + ((lane) & 7)) * 144             \
                          + ((lane) >> 3) * 16;                                 \
        _Pragma("unroll")                                                       \
        for (int nt = 0; nt < 4; nt++) {                                        \
            uint32_t ba = baddr0 + nt * 8 * 144;                                \
            uint32_t b0, b1, b2, b3, b4, b5, b6, b7;                            \
            asm volatile("ldmatrix.sync.aligned.m8n8.x4.shared.b16 {%0,%1,%2,%3}, [%4];" \
                         : "=r"(b0), "=r"(b1), "=r"(b2), "=r"(b3) : "r"(ba));   \
            asm volatile("ldmatrix.sync.aligned.m8n8.x4.shared.b16 {%0,%1,%2,%3}, [%4];" \
                         : "=r"(b4), "=r"(b5), "=r"(b6), "=r"(b7) : "r"(ba + 64)); \
            asm volatile("mma.sync.aligned.m16n8k16.row.col.f32.bf16.bf16.f32 " \
                         "{%0,%1,%2,%3}, {%4,%5,%6,%7}, {%8,%9}, {%0,%1,%2,%3};" \
                         : "+f"(acc[nt][0]), "+f"(acc[nt][1]),                  \
                           "+f"(acc[nt][2]), "+f"(acc[nt][3])                   \
                         : "r"(af[0][0]), "r"(af[0][1]), "r"(af[0][2]), "r"(af[0][3]), \
                           "r"(b0), "r"(b1));                                   \
            asm volatile("mma.sync.aligned.m16n8k16.row.col.f32.bf16.bf16.f32 " \
                         "{%0,%1,%2,%3}, {%4,%5,%6,%7}, {%8,%9}, {%0,%1,%2,%3};" \
                         : "+f"(acc[nt][0]), "+f"(acc[nt][1]),                  \
                           "+f"(acc[nt][2]), "+f"(acc[nt][3])                   \
                         : "r"(af[1][0]), "r"(af[1][1]), "r"(af[1][2]), "r"(af[1][3]), \
                           "r"(b2), "r"(b3));                                   \
            asm volatile("mma.sync.aligned.m16n8k16.row.col.f32.bf16.bf16.f32 " \
                         "{%0,%1,%2,%3}, {%4,%5,%6,%7}, {%8,%9}, {%0,%1,%2,%3};" \
                         : "+f"(acc[nt][0]), "+f"(acc[nt][1]),                  \
                           "+f"(acc[nt][2]), "+f"(acc[nt][3])                   \
                         : "r"(af[2][0]), "r"(af[2][1]), "r"(af[2][2]), "r"(af[2][3]), \
                           "r"(b4), "r"(b5));                                   \
            asm volatile("mma.sync.aligned.m16n8k16.row.col.f32.bf16.bf16.f32 " \
                         "{%0,%1,%2,%3}, {%4,%5,%6,%7}, {%8,%9}, {%0,%1,%2,%3};" \
                         : "+f"(acc[nt][0]), "+f"(acc[nt][1]),                  \
                           "+f"(acc[nt][2]), "+f"(acc[nt][3])                   \
                         : "r"(af[3][0]), "r"(af[3][1]), "r"(af[3][2]), "r"(af[3][3]), \
                           "r"(b6), "r"(b7));                                   \
        }                                                                       \
    } while (0)

__device__ __forceinline__ void load_A(char* smem, int tid, int k, int nbase) {
    const int4* asrc = (const int4*)&g_v1b[k][nbase][0];
    for (int f = tid; f < 512; f += 256) {
        int r = f >> 3, q = f & 7;
        *(int4*)(smem + OFF_A + r * 144 + q * 16) = asrc[f];
    }
}

// 8KB B chunk: two 16B cp.async per thread, one commit group
__device__ __forceinline__ void cp_async_B(uint32_t sbase, int tid, int k,
                                           int colbase, int cc) {
    const int4* src = (const int4*)&g_v2b[k][colbase + cc * 64][0];
#pragma unroll
    for (int f = tid; f < 512; f += 256) {
        int r = f >> 3, q = f & 7;
        uint32_t dst = sbase + OFF_B + (cc & 3) * 9216 + r * 144 + q * 16;
        asm volatile("cp.async.cg.shared.global [%0], [%1], 16;" :: "r"(dst), "l"(src + f));
    }
    asm volatile("cp.async.commit_group;");
}

__device__ __forceinline__ void preload_af(uint32_t af[4][4], uint32_t sbase, int rb, int lane) {
    uint32_t abase = sbase + OFF_A + (rb * 16 + (lane & 15)) * 144 + (lane >> 4) * 16;
#pragma unroll
    for (int ks = 0; ks < 4; ks++) {
        asm volatile("ldmatrix.sync.aligned.m8n8.x4.shared.b16 {%0,%1,%2,%3}, [%4];"
                     : "=r"(af[ks][0]), "=r"(af[ks][1]), "=r"(af[ks][2]), "=r"(af[ks][3])
                     : "r"(abase + ks * 32));
    }
}

// ---------------------------------------------------------------------------
// Pass 1: HMMA + per-row 32-col sub-chunk maxima.
// ---------------------------------------------------------------------------
__global__ void __launch_bounds__(256, 3) score1_kernel() {
    extern __shared__ char smem[];
    uint32_t sbase = smem_u32(smem);
    int tid = threadIdx.x, wid = tid >> 5, lane = tid & 31;
    int rb = wid & 3, ch = wid >> 2;
    int xq = blockIdx.x, rt = blockIdx.y;
    int j = xq >> 1, qq = xq & 1;
    int mod_i = rt >> 6;
    int k = mod_i * 2 + j;
    int nbase = (rt & 63) * 64;
    int rowg0 = rt * 64;
    int colbase = qq * 2048;

    load_A(smem, tid, k, nbase);
    cp_async_B(sbase, tid, k, colbase, 0);
    cp_async_B(sbase, tid, k, colbase, 1);
    cp_async_B(sbase, tid, k, colbase, 2);
    __syncthreads();

    uint32_t af[4][4];
    preload_af(af, sbase, rb, lane);

    int drow = rb * 16 + (lane >> 2);

    for (int cc = 0; cc < 32; cc++) {
        asm volatile("cp.async.wait_group 2;");
        __syncthreads();
        if (cc + 3 < 32) cp_async_B(sbase, tid, k, colbase, cc + 3);

        uint32_t bbuf = sbase + OFF_B + (cc & 3) * 9216;
        float acc[4][4];
#pragma unroll
        for (int nt = 0; nt < 4; nt++)
#pragma unroll
            for (int s = 0; s < 4; s++) acc[nt][s] = 0.f;
        MMA_CHUNK4(acc, af, bbuf, ch, lane);

        float mlo = acc[0][0], mhi = acc[0][2];
#pragma unroll
        for (int nt = 0; nt < 4; nt++) {
            mlo = fmaxf(mlo, fmaxf(acc[nt][0], acc[nt][1]));
            mhi = fmaxf(mhi, fmaxf(acc[nt][2], acc[nt][3]));
        }
        mlo = fmaxf(mlo, __shfl_xor_sync(FULLM, mlo, 1));
        mlo = fmaxf(mlo, __shfl_xor_sync(FULLM, mlo, 2));
        mhi = fmaxf(mhi, __shfl_xor_sync(FULLM, mhi, 1));
        mhi = fmaxf(mhi, __shfl_xor_sync(FULLM, mhi, 2));
        if ((lane & 3) == 0) {
            int cmi = j * 128 + qq * 64 + cc * 2 + ch;
            g_cm[rowg0 + drow][cmi]     = mlo;
            g_cm[rowg0 + drow + 8][cmi] = mhi;
        }
    }
}

// ---------------------------------------------------------------------------
// Threshold: T[row] = (20th largest of 256 sub-chunk maxima) - DELTA.
// ---------------------------------------------------------------------------
__global__ void thr_kernel() {
    int w = threadIdx.x >> 5, lane = threadIdx.x & 31;
    int row = blockIdx.x * 8 + w;

    float a[8];
#pragma unroll
    for (int s = 0; s < 8; s++) a[s] = g_cm[row][lane + 32 * s];

    float last = -1e30f;
#pragma unroll
    for (int kk = 0; kk < KTOP; kk++) {
        float bv = a[0];
#pragma unroll
        for (int s = 1; s < 8; s++) bv = fmaxf(bv, a[s]);
#pragma unroll
        for (int off = 16; off > 0; off >>= 1)
            bv = fmaxf(bv, __shfl_xor_sync(FULLM, bv, off));
#pragma unroll
        for (int s = 0; s < 8; s++) a[s] = (a[s] == bv) ? -1e30f : a[s];
        last = bv;
    }
    if (lane == 0) g_T[row] = last - DELTA;
}

// ---------------------------------------------------------------------------
// Pass 2: HMMA + filter-append values > T into per-row FIFOs.
// smem: A+4B(46080) + fv 64*48*4 @46080 + fc @58368 + cnt @64512 = 64768.
// ---------------------------------------------------------------------------
#define OFF_FV 46080
#define OFF_FC 58368
#define OFF_CN 64512
#define SM2_TOTAL 64768

__global__ void __launch_bounds__(256, 3) score2_kernel() {
    extern __shared__ char smem[];
    uint32_t sbase = smem_u32(smem);
    int tid = threadIdx.x, wid = tid >> 5, lane = tid & 31;
    int rb = wid & 3, ch = wid >> 2;
    int xq = blockIdx.x, rt = blockIdx.y;
    int j = xq >> 1, qq = xq & 1;
    int mod_i = rt >> 6;
    int k = mod_i * 2 + j;
    int nbase = (rt & 63) * 64;
    int rowg0 = rt * 64;
    int colbase = qq * 2048;

    float* fv = (float*)(smem + OFF_FV);
    unsigned short* fc = (unsigned short*)(smem + OFF_FC);
    int* cnt = (int*)(smem + OFF_CN);
    if (tid < 64) cnt[tid] = 0;

    load_A(smem, tid, k, nbase);
    cp_async_B(sbase, tid, k, colbase, 0);
    cp_async_B(sbase, tid, k, colbase, 1);
    cp_async_B(sbase, tid, k, colbase, 2);
    __syncthreads();

    uint32_t af[4][4];
    preload_af(af, sbase, rb, lane);

    int drow = rb * 16 + (lane >> 2);
    int dcol = (lane & 3) * 2;
    float Tlo = g_T[rowg0 + drow];
    float Thi = g_T[rowg0 + drow + 8];
    int cbase = j * 4096 + colbase;

    for (int cc = 0; cc < 32; cc++) {
        asm volatile("cp.async.wait_group 2;");
        __syncthreads();
        if (cc + 3 < 32) cp_async_B(sbase, tid, k, colbase, cc + 3);

        uint32_t bbuf = sbase + OFF_B + (cc & 3) * 9216;
        float acc[4][4];
#pragma unroll
        for (int nt = 0; nt < 4; nt++)
#pragma unroll
            for (int s = 0; s < 4; s++) acc[nt][s] = 0.f;
        MMA_CHUNK4(acc, af, bbuf, ch, lane);

#pragma unroll
        for (int nt = 0; nt < 4; nt++) {
            int colb = cbase + cc * 64 + ch * 32 + nt * 8 + dcol;
            if (acc[nt][0] > Tlo) {
                int p = atomicAdd(&cnt[drow], 1);
                if (p < CAND) { fv[drow * CAND + p] = acc[nt][0];
                                fc[drow * CAND + p] = (unsigned short)colb; }
            }
            if (acc[nt][1] > Tlo) {
                int p = atomicAdd(&cnt[drow], 1);
                if (p < CAND) { fv[drow * CAND + p] = acc[nt][1];
                                fc[drow * CAND + p] = (unsigned short)(colb + 1); }
            }
            if (acc[nt][2] > Thi) {
                int p = atomicAdd(&cnt[drow + 8], 1);
                if (p < CAND) { fv[(drow + 8) * CAND + p] = acc[nt][2];
                                fc[(drow + 8) * CAND + p] = (unsigned short)colb; }
            }
            if (acc[nt][3] > Thi) {
                int p = atomicAdd(&cnt[drow + 8], 1);
                if (p < CAND) { fv[(drow + 8) * CAND + p] = acc[nt][3];
                                fc[(drow + 8) * CAND + p] = (unsigned short)(colb + 1); }
            }
        }
    }
    __syncthreads();

    for (int t = tid; t < 64 * CAND; t += 256) {
        int r = t / CAND, i = t % CAND;
        int n = min(cnt[r], CAND);
        g_cval[rowg0 + r][xq * CAND + i] = (i < n) ? fv[t] : -1e30f;
        g_ccol[rowg0 + r][xq * CAND + i] = fc[t];
    }
}

// ---------------------------------------------------------------------------
// Merge (+fused zero): block = 8 rows, warp/row. 192 candidates:
// pass-1 bf16 20th -> fp32 rescore of survivors -> pass-2 top-20 -> scatter.
// ---------------------------------------------------------------------------
__global__ void merge_rescore_kernel(float* __restrict__ out) {
    __shared__ float sv1[8][2][64];
    int tid = threadIdx.x;
    int w = tid >> 5, lane = tid & 31;
    int row0 = blockIdx.x * 8;
    int row = row0 + w;
    int mod_i = row >> 12, rloc = row & 4095;

    {
        float4* ob = (float4*)(out + (size_t)row0 * NROWS);
        for (int t = tid; t < 8 * NROWS / 4; t += 256)
            ob[t] = make_float4(0.f, 0.f, 0.f, 0.f);
    }

    for (int t = lane; t < 128; t += 32) {
        int h = t >> 6, d = t & 63;
        sv1[w][h][d] = g_v1[mod_i * 2 + h][rloc][d];
    }
    __syncthreads();

    float wv[6]; int col[6];
#pragma unroll
    for (int s = 0; s < 6; s++) {
        int idx = lane * 6 + s;
        wv[s]  = g_cval[row][idx];
        col[s] = (int)g_ccol[row][idx];
    }

    // pass 1: 20th-largest bf16-level candidate (value-only rounds)
    float a0 = wv[0], a1 = wv[1], a2 = wv[2], a3 = wv[3], a4 = wv[4], a5 = wv[5];
    float thr = 0.f;
#pragma unroll
    for (int kk = 0; kk < KTOP; kk++) {
        float bv = fmaxf(fmaxf(fmaxf(a0, a1), fmaxf(a2, a3)), fmaxf(a4, a5));
#pragma unroll
        for (int off = 16; off > 0; off >>= 1)
            bv = fmaxf(bv, __shfl_xor_sync(FULLM, bv, off));
        a0 = (a0 == bv) ? -1e30f : a0;
        a1 = (a1 == bv) ? -1e30f : a1;
        a2 = (a2 == bv) ? -1e30f : a2;
        a3 = (a3 == bv) ? -1e30f : a3;
        a4 = (a4 == bv) ? -1e30f : a4;
        a5 = (a5 == bv) ? -1e30f : a5;
        thr = bv;
    }

    // rescore survivors in exact fp32
    float rv[6];
#pragma unroll
    for (int s = 0; s < 6; s++) {
        if (wv[s] >= thr - DELTA) {
            int h = col[s] >> 12, cl = col[s] & 4095;
            const float4* v2c = (const float4*)&g_v2[mod_i * 2 + h][cl][0];
            const float4* v1c = (const float4*)&sv1[w][h][0];
            float acc = 0.f;
#pragma unroll
            for (int dd = 0; dd < 16; dd++) {
                float4 x = v1c[dd], y = v2c[dd];
                acc += x.x * y.x + x.y * y.y + x.z * y.z + x.w * y.w;
            }
            rv[s] = acc;
        } else {
            rv[s] = -1e30f;
        }
    }

    // pass 2: exact top-20, scatter tanh
#pragma unroll
    for (int kk = 0; kk < KTOP; kk++) {
        float bv = rv[0]; int bs = 0;
        if (rv[1] > bv) { bv = rv[1]; bs = 1; }
        if (rv[2] > bv) { bv = rv[2]; bs = 2; }
        if (rv[3] > bv) { bv = rv[3]; bs = 3; }
        if (rv[4] > bv) { bv = rv[4]; bs = 4; }
        if (rv[5] > bv) { bv = rv[5]; bs = 5; }
        int bc = col[bs];
        int bi = lane * 8 + bs;
#pragma unroll
        for (int off = 16; off > 0; off >>= 1) {
            float ov = __shfl_xor_sync(FULLM, bv, off);
            int   oc = __shfl_xor_sync(FULLM, bc, off);
            int   oi = __shfl_xor_sync(FULLM, bi, off);
            if (ov > bv || (ov == bv && oi < bi)) { bv = ov; bc = oc; bi = oi; }
        }
        if (lane == (bi >> 3)) rv[bi & 7] = -1e30f;
        if (lane == kk) {
            float t = (bv > 0.f) ? tanhf(3.0f * bv) : 0.f;
            out[(size_t)row * NROWS + bc] = t;
        }
    }
}

// ---------------------------------------------------------------------------
extern "C" void kernel_launch(void* const* d_in, const int* in_sizes, int n_in,
                              void* d_out, int out_size) {
    const float* emb1 = (const float*)d_in[1];
    const float* emb2 = (const float*)d_in[2];
    const float* w1   = (const float*)d_in[3];
    const float* w2   = (const float*)d_in[4];
    const float* b1   = (const float*)d_in[5];
    const float* b2   = (const float*)d_in[6];
    float* out = (float*)d_out;

    cudaFuncSetAttribute(score1_kernel,
                         cudaFuncAttributeMaxDynamicSharedMemorySize, SM_AB);
    cudaFuncSetAttribute(score2_kernel,
                         cudaFuncAttributeMaxDynamicSharedMemorySize, SM2_TOTAL);

    compute_v_kernel<<<dim3(64, NMAT, 2), 256>>>(emb1, emb2, w1, w2, b1, b2);
    score1_kernel<<<dim3(4, 128), 256, SM_AB>>>();
    thr_kernel<<<NROWS / 8, 256>>>();
    score2_kernel<<<dim3(4, 128), 256, SM2_TOTAL>>>();
    merge_rescore_kernel<<<NROWS / 8, 256>>>(out);
}

// round 13
// speedup vs baseline: 1.0233x; 1.0233x over previous
#include <cuda_runtime.h>
#include <cuda_bf16.h>
#include <math.h>
#include <stdint.h>

#define NMAT 4
#define NSUB 4096
#define DIM 64
#define KTOP 20
#define NROWS 8192
#define DELTA 0.008f
#define FULLM 0xffffffffu
#define CAND 48            // candidates per half-row

// device global scratch (no allocation allowed)
__device__ float g_v1[NMAT][NSUB][DIM];
__device__ float g_v2[NMAT][NSUB][DIM];
__device__ __nv_bfloat16 g_v1b[NMAT][NSUB][DIM];
__device__ __nv_bfloat16 g_v2b[NMAT][NSUB][DIM];
__device__ float          g_cm[NROWS][256];       // per-row 32-col sub-chunk maxima
__device__ float          g_T[NROWS];             // per-row filter threshold
__device__ float          g_cval[NROWS][2 * CAND];
__device__ unsigned short g_ccol[NROWS][2 * CAND];

__device__ __forceinline__ uint32_t smem_u32(const void* p) {
    uint32_t a;
    asm("{ .reg .u64 t; cvta.to.shared.u64 t, %1; cvt.u32.u64 %0, t; }" : "=r"(a) : "l"(p));
    return a;
}

// ---------------------------------------------------------------------------
// v = emb @ w + b (fp32) + bf16 copy
// ---------------------------------------------------------------------------
__global__ void compute_v_kernel(const float* __restrict__ emb1,
                                 const float* __restrict__ emb2,
                                 const float* __restrict__ w1,
                                 const float* __restrict__ w2,
                                 const float* __restrict__ b1,
                                 const float* __restrict__ b2) {
    int which = blockIdx.z;
    int k = blockIdx.y;
    int tile = blockIdx.x;
    const float* emb = which ? emb2 : emb1;
    const float* w   = which ? w2   : w1;
    const float* b   = which ? b2   : b1;
    float* vout            = which ? &g_v2[0][0][0]  : &g_v1[0][0][0];
    __nv_bfloat16* voutb   = which ? &g_v2b[0][0][0] : &g_v1b[0][0][0];

    __shared__ float semb[64 * 65];
    __shared__ float sw[64 * 64];
    __shared__ float sb[64];

    int tid = threadIdx.x;
    for (int t = tid; t < 4096; t += 256) {
        int r = t >> 6, e = t & 63;
        semb[r * 65 + e] = emb[(size_t)(k * NSUB + tile * 64 + r) * 64 + e];
        sw[t] = w[k * 4096 + t];
    }
    if (tid < 64) sb[tid] = b[k * 64 + tid];
    __syncthreads();

    int nl = tid & 63, q = tid >> 6;
    float acc[16];
#pragma unroll
    for (int d = 0; d < 16; d++) acc[d] = 0.f;

#pragma unroll 4
    for (int e = 0; e < 64; e++) {
        float a = semb[nl * 65 + e];
#pragma unroll
        for (int jj = 0; jj < 4; jj++) {
            float4 wv = *(const float4*)&sw[e * 64 + q * 16 + jj * 4];
            acc[jj * 4 + 0] += a * wv.x;
            acc[jj * 4 + 1] += a * wv.y;
            acc[jj * 4 + 2] += a * wv.z;
            acc[jj * 4 + 3] += a * wv.w;
        }
    }

    size_t rowoff = (size_t)(k * NSUB + tile * 64 + nl) * 64;
    float* orow = vout + rowoff;
    __nv_bfloat16* orowb = voutb + rowoff;
#pragma unroll
    for (int dd = 0; dd < 16; dd++) {
        int d = q * 16 + dd;
        float v = acc[dd] + sb[d];
        orow[d]  = v;
        orowb[d] = __float2bfloat16(v);
    }
}

// ---------------------------------------------------------------------------
// HMMA plumbing. 512 threads, 128-row tile, 128-col chunks (32 iterations).
// warp w = (rowband rb = w&7) x (colhalf ch = w>>3); warp: 16 rows x 64 cols.
// B: 4-stage cp.async ring (18432B/stage), 3-deep prefetch. ldmatrix.x4.
// ---------------------------------------------------------------------------
#define OFF_A  0
#define OFF_B  18432
#define BSTAGE 18432
#define SM_AB  (OFF_B + 4 * BSTAGE)   // 92160

// 8 n-tiles: nt 0-3 = first 32 cols of warp's 64, nt 4-7 = second 32
#define MMA_CHUNK8(acc, af, bbuf, ch, lane)                                     \
    do {                                                                        \
        uint32_t baddr0 = (bbuf) + ((ch) * 64 + ((lane) & 7)) * 144             \
                          + ((lane) >> 3) * 16;                                 \
        _Pragma("unroll")                                                       \
        for (int nt = 0; nt < 8; nt++) {                                        \
            uint32_t ba = baddr0 + nt * 8 * 144;                                \
            uint32_t b0, b1, b2, b3, b4, b5, b6, b7;                            \
            asm volatile("ldmatrix.sync.aligned.m8n8.x4.shared.b16 {%0,%1,%2,%3}, [%4];" \
                         : "=r"(b0), "=r"(b1), "=r"(b2), "=r"(b3) : "r"(ba));   \
            asm volatile("ldmatrix.sync.aligned.m8n8.x4.shared.b16 {%0,%1,%2,%3}, [%4];" \
                         : "=r"(b4), "=r"(b5), "=r"(b6), "=r"(b7) : "r"(ba + 64)); \
            asm volatile("mma.sync.aligned.m16n8k16.row.col.f32.bf16.bf16.f32 " \
                         "{%0,%1,%2,%3}, {%4,%5,%6,%7}, {%8,%9}, {%0,%1,%2,%3};" \
                         : "+f"(acc[nt][0]), "+f"(acc[nt][1]),                  \
                           "+f"(acc[nt][2]), "+f"(acc[nt][3])                   \
                         : "r"(af[0][0]), "r"(af[0][1]), "r"(af[0][2]), "r"(af[0][3]), \
                           "r"(b0), "r"(b1));                                   \
            asm volatile("mma.sync.aligned.m16n8k16.row.col.f32.bf16.bf16.f32 " \
                         "{%0,%1,%2,%3}, {%4,%5,%6,%7}, {%8,%9}, {%0,%1,%2,%3};" \
                         : "+f"(acc[nt][0]), "+f"(acc[nt][1]),                  \
                           "+f"(acc[nt][2]), "+f"(acc[nt][3])                   \
                         : "r"(af[1][0]), "r"(af[1][1]), "r"(af[1][2]), "r"(af[1][3]), \
                           "r"(b2), "r"(b3));                                   \
            asm volatile("mma.sync.aligned.m16n8k16.row.col.f32.bf16.bf16.f32 " \
                         "{%0,%1,%2,%3}, {%4,%5,%6,%7}, {%8,%9}, {%0,%1,%2,%3};" \
                         : "+f"(acc[nt][0]), "+f"(acc[nt][1]),                  \
                           "+f"(acc[nt][2]), "+f"(acc[nt][3])                   \
                         : "r"(af[2][0]), "r"(af[2][1]), "r"(af[2][2]), "r"(af[2][3]), \
                           "r"(b4), "r"(b5));                                   \
            asm volatile("mma.sync.aligned.m16n8k16.row.col.f32.bf16.bf16.f32 " \
                         "{%0,%1,%2,%3}, {%4,%5,%6,%7}, {%8,%9}, {%0,%1,%2,%3};" \
                         : "+f"(acc[nt][0]), "+f"(acc[nt][1]),                  \
                           "+f"(acc[nt][2]), "+f"(acc[nt][3])                   \
                         : "r"(af[3][0]), "r"(af[3][1]), "r"(af[3][2]), "r"(af[3][3]), \
                           "r"(b6), "r"(b7));                                   \
        }                                                                       \
    } while (0)

__device__ __forceinline__ void load_A(char* smem, int tid, int k, int nbase) {
    const int4* asrc = (const int4*)&g_v1b[k][nbase][0];
    for (int f = tid; f < 1024; f += 512) {
        int r = f >> 3, q = f & 7;
        *(int4*)(smem + OFF_A + r * 144 + q * 16) = asrc[f];
    }
}

// 16KB B chunk (128 rows): two 16B cp.async per thread, one commit group
__device__ __forceinline__ void cp_async_B(uint32_t sbase, int tid, int k, int cc) {
    const int4* src = (const int4*)&g_v2b[k][cc * 128][0];
#pragma unroll
    for (int f = tid; f < 1024; f += 512) {
        int r = f >> 3, q = f & 7;
        uint32_t dst = sbase + OFF_B + (cc & 3) * BSTAGE + r * 144 + q * 16;
        asm volatile("cp.async.cg.shared.global [%0], [%1], 16;" :: "r"(dst), "l"(src + f));
    }
    asm volatile("cp.async.commit_group;");
}

__device__ __forceinline__ void preload_af(uint32_t af[4][4], uint32_t sbase, int rb, int lane) {
    uint32_t abase = sbase + OFF_A + (rb * 16 + (lane & 15)) * 144 + (lane >> 4) * 16;
#pragma unroll
    for (int ks = 0; ks < 4; ks++) {
        asm volatile("ldmatrix.sync.aligned.m8n8.x4.shared.b16 {%0,%1,%2,%3}, [%4];"
                     : "=r"(af[ks][0]), "=r"(af[ks][1]), "=r"(af[ks][2]), "=r"(af[ks][3])
                     : "r"(abase + ks * 32));
    }
}

// ---------------------------------------------------------------------------
// Pass 1: HMMA + per-row 32-col sub-chunk maxima. grid (half:2, rowtile:64).
// ---------------------------------------------------------------------------
__global__ void __launch_bounds__(512, 1) score1_kernel() {
    extern __shared__ char smem[];
    uint32_t sbase = smem_u32(smem);
    int tid = threadIdx.x, wid = tid >> 5, lane = tid & 31;
    int rb = wid & 7, ch = wid >> 3;
    int half = blockIdx.x, rt = blockIdx.y;
    int k = (rt >> 5) * 2 + half;
    int nbase = (rt & 31) * 128;
    int rowg0 = rt * 128;

    load_A(smem, tid, k, nbase);
    cp_async_B(sbase, tid, k, 0);
    cp_async_B(sbase, tid, k, 1);
    cp_async_B(sbase, tid, k, 2);
    __syncthreads();

    uint32_t af[4][4];
    preload_af(af, sbase, rb, lane);

    int drow = rb * 16 + (lane >> 2);

    for (int cc = 0; cc < 32; cc++) {
        asm volatile("cp.async.wait_group 2;");
        __syncthreads();
        if (cc + 3 < 32) cp_async_B(sbase, tid, k, cc + 3);

        uint32_t bbuf = sbase + OFF_B + (cc & 3) * BSTAGE;
        float acc[8][4];
#pragma unroll
        for (int nt = 0; nt < 8; nt++)
#pragma unroll
            for (int s = 0; s < 4; s++) acc[nt][s] = 0.f;
        MMA_CHUNK8(acc, af, bbuf, ch, lane);

        // two 32-col sub-chunk maxima per lane per row
#pragma unroll
        for (int g = 0; g < 2; g++) {
            float mlo = acc[g * 4][0], mhi = acc[g * 4][2];
#pragma unroll
            for (int nt = g * 4; nt < g * 4 + 4; nt++) {
                mlo = fmaxf(mlo, fmaxf(acc[nt][0], acc[nt][1]));
                mhi = fmaxf(mhi, fmaxf(acc[nt][2], acc[nt][3]));
            }
            mlo = fmaxf(mlo, __shfl_xor_sync(FULLM, mlo, 1));
            mlo = fmaxf(mlo, __shfl_xor_sync(FULLM, mlo, 2));
            mhi = fmaxf(mhi, __shfl_xor_sync(FULLM, mhi, 1));
            mhi = fmaxf(mhi, __shfl_xor_sync(FULLM, mhi, 2));
            if ((lane & 3) == 0) {
                int cmi = half * 128 + cc * 4 + ch * 2 + g;
                g_cm[rowg0 + drow][cmi]     = mlo;
                g_cm[rowg0 + drow + 8][cmi] = mhi;
            }
        }
    }
}

// ---------------------------------------------------------------------------
// Threshold: T[row] = (20th largest of 256 sub-chunk maxima) - DELTA.
// ---------------------------------------------------------------------------
__global__ void thr_kernel() {
    int w = threadIdx.x >> 5, lane = threadIdx.x & 31;
    int row = blockIdx.x * 8 + w;

    float a[8];
#pragma unroll
    for (int s = 0; s < 8; s++) a[s] = g_cm[row][lane + 32 * s];

    float last = -1e30f;
#pragma unroll
    for (int kk = 0; kk < KTOP; kk++) {
        float bv = a[0];
#pragma unroll
        for (int s = 1; s < 8; s++) bv = fmaxf(bv, a[s]);
#pragma unroll
        for (int off = 16; off > 0; off >>= 1)
            bv = fmaxf(bv, __shfl_xor_sync(FULLM, bv, off));
#pragma unroll
        for (int s = 0; s < 8; s++) a[s] = (a[s] == bv) ? -1e30f : a[s];
        last = bv;
    }
    if (lane == 0) g_T[row] = last - DELTA;
}

// ---------------------------------------------------------------------------
// Pass 2: HMMA + filter-append values > T into per-row FIFOs.
// smem: A+4B(92160) + fv 128*48*4 @92160 + fc @116736 + cnt @129024 = 129536.
// ---------------------------------------------------------------------------
#define OFF_FV 92160
#define OFF_FC 116736
#define OFF_CN 129024
#define SM2_TOTAL 129536

__global__ void __launch_bounds__(512, 1) score2_kernel() {
    extern __shared__ char smem[];
    uint32_t sbase = smem_u32(smem);
    int tid = threadIdx.x, wid = tid >> 5, lane = tid & 31;
    int rb = wid & 7, ch = wid >> 3;
    int half = blockIdx.x, rt = blockIdx.y;
    int k = (rt >> 5) * 2 + half;
    int nbase = (rt & 31) * 128;
    int rowg0 = rt * 128;

    float* fv = (float*)(smem + OFF_FV);
    unsigned short* fc = (unsigned short*)(smem + OFF_FC);
    int* cnt = (int*)(smem + OFF_CN);
    if (tid < 128) cnt[tid] = 0;

    load_A(smem, tid, k, nbase);
    cp_async_B(sbase, tid, k, 0);
    cp_async_B(sbase, tid, k, 1);
    cp_async_B(sbase, tid, k, 2);
    __syncthreads();

    uint32_t af[4][4];
    preload_af(af, sbase, rb, lane);

    int drow = rb * 16 + (lane >> 2);
    int dcol = (lane & 3) * 2;
    float Tlo = g_T[rowg0 + drow];
    float Thi = g_T[rowg0 + drow + 8];
    int cbase = half * 4096;

    for (int cc = 0; cc < 32; cc++) {
        asm volatile("cp.async.wait_group 2;");
        __syncthreads();
        if (cc + 3 < 32) cp_async_B(sbase, tid, k, cc + 3);

        uint32_t bbuf = sbase + OFF_B + (cc & 3) * BSTAGE;
        float acc[8][4];
#pragma unroll
        for (int nt = 0; nt < 8; nt++)
#pragma unroll
            for (int s = 0; s < 4; s++) acc[nt][s] = 0.f;
        MMA_CHUNK8(acc, af, bbuf, ch, lane);

#pragma unroll
        for (int nt = 0; nt < 8; nt++) {
            int colb = cbase + cc * 128 + ch * 64 + nt * 8 + dcol;
            if (acc[nt][0] > Tlo) {
                int p = atomicAdd(&cnt[drow], 1);
                if (p < CAND) { fv[drow * CAND + p] = acc[nt][0];
                                fc[drow * CAND + p] = (unsigned short)colb; }
            }
            if (acc[nt][1] > Tlo) {
                int p = atomicAdd(&cnt[drow], 1);
                if (p < CAND) { fv[drow * CAND + p] = acc[nt][1];
                                fc[drow * CAND + p] = (unsigned short)(colb + 1); }
            }
            if (acc[nt][2] > Thi) {
                int p = atomicAdd(&cnt[drow + 8], 1);
                if (p < CAND) { fv[(drow + 8) * CAND + p] = acc[nt][2];
                                fc[(drow + 8) * CAND + p] = (unsigned short)colb; }
            }
            if (acc[nt][3] > Thi) {
                int p = atomicAdd(&cnt[drow + 8], 1);
                if (p < CAND) { fv[(drow + 8) * CAND + p] = acc[nt][3];
                                fc[(drow + 8) * CAND + p] = (unsigned short)(colb + 1); }
            }
        }
    }
    __syncthreads();

    for (int t = tid; t < 128 * CAND; t += 512) {
        int r = t / CAND, i = t % CAND;
        int n = min(cnt[r], CAND);
        g_cval[rowg0 + r][half * CAND + i] = (i < n) ? fv[t] : -1e30f;
        g_ccol[rowg0 + r][half * CAND + i] = fc[t];
    }
}

// ---------------------------------------------------------------------------
// Merge (+fused zero): block = 8 rows, warp/row. 96 candidates:
// pass-1 bf16 20th -> fp32 rescore of survivors -> pass-2 top-20 -> scatter.
// ---------------------------------------------------------------------------
__global__ void merge_rescore_kernel(float* __restrict__ out) {
    __shared__ float sv1[8][2][64];
    int tid = threadIdx.x;
    int w = tid >> 5, lane = tid & 31;
    int row0 = blockIdx.x * 8;
    int row = row0 + w;
    int mod_i = row >> 12, rloc = row & 4095;

    {
        float4* ob = (float4*)(out + (size_t)row0 * NROWS);
        for (int t = tid; t < 8 * NROWS / 4; t += 256)
            ob[t] = make_float4(0.f, 0.f, 0.f, 0.f);
    }

    for (int t = lane; t < 128; t += 32) {
        int h = t >> 6, d = t & 63;
        sv1[w][h][d] = g_v1[mod_i * 2 + h][rloc][d];
    }
    __syncthreads();

    float wv[3]; int col[3];
#pragma unroll
    for (int s = 0; s < 3; s++) {
        int idx = lane * 3 + s;
        wv[s]  = g_cval[row][idx];
        col[s] = (int)g_ccol[row][idx];
    }

    // pass 1: 20th-largest bf16-level candidate (value-only rounds;
    // duplicate clearing lowers thr -> conservative)
    float a0 = wv[0], a1 = wv[1], a2 = wv[2];
    float thr = 0.f;
#pragma unroll
    for (int kk = 0; kk < KTOP; kk++) {
        float bv = fmaxf(fmaxf(a0, a1), a2);
#pragma unroll
        for (int off = 16; off > 0; off >>= 1)
            bv = fmaxf(bv, __shfl_xor_sync(FULLM, bv, off));
        a0 = (a0 == bv) ? -1e30f : a0;
        a1 = (a1 == bv) ? -1e30f : a1;
        a2 = (a2 == bv) ? -1e30f : a2;
        thr = bv;
    }

    // rescore survivors in exact fp32
    float rv[3];
#pragma unroll
    for (int s = 0; s < 3; s++) {
        if (wv[s] >= thr - DELTA) {
            int h = col[s] >> 12, cl = col[s] & 4095;
            const float4* v2c = (const float4*)&g_v2[mod_i * 2 + h][cl][0];
            const float4* v1c = (const float4*)&sv1[w][h][0];
            float acc = 0.f;
#pragma unroll
            for (int dd = 0; dd < 16; dd++) {
                float4 x = v1c[dd], y = v2c[dd];
                acc += x.x * y.x + x.y * y.y + x.z * y.z + x.w * y.w;
            }
            rv[s] = acc;
        } else {
            rv[s] = -1e30f;
        }
    }

    // pass 2: exact top-20, scatter tanh
#pragma unroll
    for (int kk = 0; kk < KTOP; kk++) {
        float bv = rv[0]; int bs = 0;
        if (rv[1] > bv) { bv = rv[1]; bs = 1; }
        if (rv[2] > bv) { bv = rv[2]; bs = 2; }
        int bc = col[bs];
        int bi = lane * 4 + bs;
#pragma unroll
        for (int off = 16; off > 0; off >>= 1) {
            float ov = __shfl_xor_sync(FULLM, bv, off);
            int   oc = __shfl_xor_sync(FULLM, bc, off);
            int   oi = __shfl_xor_sync(FULLM, bi, off);
            if (ov > bv || (ov == bv && oi < bi)) { bv = ov; bc = oc; bi = oi; }
        }
        if (lane == (bi >> 2)) rv[bi & 3] = -1e30f;
        if (lane == kk) {
            float t = (bv > 0.f) ? tanhf(3.0f * bv) : 0.f;
            out[(size_t)row * NROWS + bc] = t;
        }
    }
}

// ---------------------------------------------------------------------------
extern "C" void kernel_launch(void* const* d_in, const int* in_sizes, int n_in,
                              void* d_out, int out_size) {
    const float* emb1 = (const float*)d_in[1];
    const float* emb2 = (const float*)d_in[2];
    const float* w1   = (const float*)d_in[3];
    const float* w2   = (const float*)d_in[4];
    const float* b1   = (const float*)d_in[5];
    const float* b2   = (const float*)d_in[6];
    float* out = (float*)d_out;

    cudaFuncSetAttribute(score1_kernel,
                         cudaFuncAttributeMaxDynamicSharedMemorySize, SM_AB);
    cudaFuncSetAttribute(score2_kernel,
                         cudaFuncAttributeMaxDynamicSharedMemorySize, SM2_TOTAL);

    compute_v_kernel<<<dim3(64, NMAT, 2), 256>>>(emb1, emb2, w1, w2, b1, b2);
    score1_kernel<<<dim3(2, 64), 512, SM_AB>>>();
    thr_kernel<<<NROWS / 8, 256>>>();
    score2_kernel<<<dim3(2, 64), 512, SM2_TOTAL>>>();
    merge_rescore_kernel<<<NROWS / 8, 256>>>(out);
}

// round 15
// speedup vs baseline: 1.1286x; 1.1030x over previous
#include <cuda_runtime.h>
#include <cuda_bf16.h>
#include <math.h>
#include <stdint.h>

#define NMAT 4
#define NSUB 4096
#define DIM 64
#define KTOP 20
#define NROWS 8192
#define DELTA 0.008f
#define FULLM 0xffffffffu
#define CAND 32            // candidates per quarter-row

// device global scratch (no allocation allowed)
__device__ float g_v1[NMAT][NSUB][DIM];
__device__ float g_v2[NMAT][NSUB][DIM];
__device__ __nv_bfloat16 g_v1b[NMAT][NSUB][DIM];
__device__ __nv_bfloat16 g_v2b[NMAT][NSUB][DIM];
__device__ float          g_cm[NROWS][256];       // per-row 32-col sub-chunk maxima
__device__ float          g_T[NROWS];             // per-row filter threshold
__device__ float          g_cval[NROWS][4 * CAND];
__device__ unsigned short g_ccol[NROWS][4 * CAND];

__device__ __forceinline__ uint32_t smem_u32(const void* p) {
    uint32_t a;
    asm("{ .reg .u64 t; cvta.to.shared.u64 t, %1; cvt.u32.u64 %0, t; }" : "=r"(a) : "l"(p));
    return a;
}

// ---------------------------------------------------------------------------
// v = emb @ w + b (fp32) + bf16 copy
// ---------------------------------------------------------------------------
__global__ void compute_v_kernel(const float* __restrict__ emb1,
                                 const float* __restrict__ emb2,
                                 const float* __restrict__ w1,
                                 const float* __restrict__ w2,
                                 const float* __restrict__ b1,
                                 const float* __restrict__ b2) {
    int which = blockIdx.z;
    int k = blockIdx.y;
    int tile = blockIdx.x;
    const float* emb = which ? emb2 : emb1;
    const float* w   = which ? w2   : w1;
    const float* b   = which ? b2   : b1;
    float* vout            = which ? &g_v2[0][0][0]  : &g_v1[0][0][0];
    __nv_bfloat16* voutb   = which ? &g_v2b[0][0][0] : &g_v1b[0][0][0];

    __shared__ float semb[64 * 65];
    __shared__ float sw[64 * 64];
    __shared__ float sb[64];

    int tid = threadIdx.x;
    for (int t = tid; t < 4096; t += 256) {
        int r = t >> 6, e = t & 63;
        semb[r * 65 + e] = emb[(size_t)(k * NSUB + tile * 64 + r) * 64 + e];
        sw[t] = w[k * 4096 + t];
    }
    if (tid < 64) sb[tid] = b[k * 64 + tid];
    __syncthreads();

    int nl = tid & 63, q = tid >> 6;
    float acc[16];
#pragma unroll
    for (int d = 0; d < 16; d++) acc[d] = 0.f;

#pragma unroll 4
    for (int e = 0; e < 64; e++) {
        float a = semb[nl * 65 + e];
#pragma unroll
        for (int jj = 0; jj < 4; jj++) {
            float4 wv = *(const float4*)&sw[e * 64 + q * 16 + jj * 4];
            acc[jj * 4 + 0] += a * wv.x;
            acc[jj * 4 + 1] += a * wv.y;
            acc[jj * 4 + 2] += a * wv.z;
            acc[jj * 4 + 3] += a * wv.w;
        }
    }

    size_t rowoff = (size_t)(k * NSUB + tile * 64 + nl) * 64;
    float* orow = vout + rowoff;
    __nv_bfloat16* orowb = voutb + rowoff;
#pragma unroll
    for (int dd = 0; dd < 16; dd++) {
        int d = q * 16 + dd;
        float v = acc[dd] + sb[d];
        orow[d]  = v;
        orowb[d] = __float2bfloat16(v);
    }
}

// ---------------------------------------------------------------------------
// HMMA plumbing. 256 threads, 64-row x 2048-col tile (32 chunks of 64 cols).
// warp w = (rowband rb = w&3) x (colhalf ch = w>>2); warp does 16 rows x 32 cols.
// B: 4-stage cp.async ring, 3-deep prefetch. B frags via ldmatrix.x4.
// grid = (xq: 4 [colmodule j = xq>>1, quarter qq = xq&1], rowtile: 128).
// ---------------------------------------------------------------------------
#define OFF_A  0
#define OFF_B  9216
#define SM_AB  46080            // A(9216) + 4 B stages (4x9216)

#define MMA_CHUNK4(acc, af, bbuf, ch, lane)                                     \
    do {                                                                        \
        uint32_t baddr0 = (bbuf) + ((ch) * 32 + ((lane) & 7)) * 144             \
                          + ((lane) >> 3) * 16;                                 \
        _Pragma("unroll")                                                       \
        for (int nt = 0; nt < 4; nt++) {                                        \
            uint32_t ba = baddr0 + nt * 8 * 144;                                \
            uint32_t b0, b1, b2, b3, b4, b5, b6, b7;                            \
            asm volatile("ldmatrix.sync.aligned.m8n8.x4.shared.b16 {%0,%1,%2,%3}, [%4];" \
                         : "=r"(b0), "=r"(b1), "=r"(b2), "=r"(b3) : "r"(ba));   \
            asm volatile("ldmatrix.sync.aligned.m8n8.x4.shared.b16 {%0,%1,%2,%3}, [%4];" \
                         : "=r"(b4), "=r"(b5), "=r"(b6), "=r"(b7) : "r"(ba + 64)); \
            asm volatile("mma.sync.aligned.m16n8k16.row.col.f32.bf16.bf16.f32 " \
                         "{%0,%1,%2,%3}, {%4,%5,%6,%7}, {%8,%9}, {%0,%1,%2,%3};" \
                         : "+f"(acc[nt][0]), "+f"(acc[nt][1]),                  \
                           "+f"(acc[nt][2]), "+f"(acc[nt][3])                   \
                         : "r"(af[0][0]), "r"(af[0][1]), "r"(af[0][2]), "r"(af[0][3]), \
                           "r"(b0), "r"(b1));                                   \
            asm volatile("mma.sync.aligned.m16n8k16.row.col.f32.bf16.bf16.f32 " \
                         "{%0,%1,%2,%3}, {%4,%5,%6,%7}, {%8,%9}, {%0,%1,%2,%3};" \
                         : "+f"(acc[nt][0]), "+f"(acc[nt][1]),                  \
                           "+f"(acc[nt][2]), "+f"(acc[nt][3])                   \
                         : "r"(af[1][0]), "r"(af[1][1]), "r"(af[1][2]), "r"(af[1][3]), \
                           "r"(b2), "r"(b3));                                   \
            asm volatile("mma.sync.aligned.m16n8k16.row.col.f32.bf16.bf16.f32 " \
                         "{%0,%1,%2,%3}, {%4,%5,%6,%7}, {%8,%9}, {%0,%1,%2,%3};" \
                         : "+f"(acc[nt][0]), "+f"(acc[nt][1]),                  \
                           "+f"(acc[nt][2]), "+f"(acc[nt][3])                   \
                         : "r"(af[2][0]), "r"(af[2][1]), "r"(af[2][2]), "r"(af[2][3]), \
                           "r"(b4), "r"(b5));                                   \
            asm volatile("mma.sync.aligned.m16n8k16.row.col.f32.bf16.bf16.f32 " \
                         "{%0,%1,%2,%3}, {%4,%5,%6,%7}, {%8,%9}, {%0,%1,%2,%3};" \
                         : "+f"(acc[nt][0]), "+f"(acc[nt][1]),                  \
                           "+f"(acc[nt][2]), "+f"(acc[nt][3])                   \
                         : "r"(af[3][0]), "r"(af[3][1]), "r"(af[3][2]), "r"(af[3][3]), \
                           "r"(b6), "r"(b7));                                   \
        }                                                                       \
    } while (0)

__device__ __forceinline__ void load_A(char* smem, int tid, int k, int nbase) {
    const int4* asrc = (const int4*)&g_v1b[k][nbase][0];
    for (int f = tid; f < 512; f += 256) {
        int r = f >> 3, q = f & 7;
        *(int4*)(smem + OFF_A + r * 144 + q * 16) = asrc[f];
    }
}

// 8KB B chunk: two 16B cp.async per thread, one commit group
__device__ __forceinline__ void cp_async_B(uint32_t sbase, int tid, int k,
                                           int colbase, int cc) {
    const int4* src = (const int4*)&g_v2b[k][colbase + cc * 64][0];
#pragma unroll
    for (int f = tid; f < 512; f += 256) {
        int r = f >> 3, q = f & 7;
        uint32_t dst = sbase + OFF_B + (cc & 3) * 9216 + r * 144 + q * 16;
        asm volatile("cp.async.cg.shared.global [%0], [%1], 16;" :: "r"(dst), "l"(src + f));
    }
    asm volatile("cp.async.commit_group;");
}

__device__ __forceinline__ void preload_af(uint32_t af[4][4], uint32_t sbase, int rb, int lane) {
    uint32_t abase = sbase + OFF_A + (rb * 16 + (lane & 15)) * 144 + (lane >> 4) * 16;
#pragma unroll
    for (int ks = 0; ks < 4; ks++) {
        asm volatile("ldmatrix.sync.aligned.m8n8.x4.shared.b16 {%0,%1,%2,%3}, [%4];"
                     : "=r"(af[ks][0]), "=r"(af[ks][1]), "=r"(af[ks][2]), "=r"(af[ks][3])
                     : "r"(abase + ks * 32));
    }
}

// ---------------------------------------------------------------------------
// Pass 1: HMMA + per-row 32-col sub-chunk maxima.
// ---------------------------------------------------------------------------
__global__ void __launch_bounds__(256, 3) score1_kernel() {
    extern __shared__ char smem[];
    uint32_t sbase = smem_u32(smem);
    int tid = threadIdx.x, wid = tid >> 5, lane = tid & 31;
    int rb = wid & 3, ch = wid >> 2;
    int xq = blockIdx.x, rt = blockIdx.y;
    int j = xq >> 1, qq = xq & 1;
    int mod_i = rt >> 6;
    int k = mod_i * 2 + j;
    int nbase = (rt & 63) * 64;
    int rowg0 = rt * 64;
    int colbase = qq * 2048;

    load_A(smem, tid, k, nbase);
    cp_async_B(sbase, tid, k, colbase, 0);
    cp_async_B(sbase, tid, k, colbase, 1);
    cp_async_B(sbase, tid, k, colbase, 2);
    __syncthreads();

    uint32_t af[4][4];
    preload_af(af, sbase, rb, lane);

    int drow = rb * 16 + (lane >> 2);

    for (int cc = 0; cc < 32; cc++) {
        asm volatile("cp.async.wait_group 2;");
        __syncthreads();
        if (cc + 3 < 32) cp_async_B(sbase, tid, k, colbase, cc + 3);

        uint32_t bbuf = sbase + OFF_B + (cc & 3) * 9216;
        float acc[4][4];
#pragma unroll
        for (int nt = 0; nt < 4; nt++)
#pragma unroll
            for (int s = 0; s < 4; s++) acc[nt][s] = 0.f;
        MMA_CHUNK4(acc, af, bbuf, ch, lane);

        float mlo = acc[0][0], mhi = acc[0][2];
#pragma unroll
        for (int nt = 0; nt < 4; nt++) {
            mlo = fmaxf(mlo, fmaxf(acc[nt][0], acc[nt][1]));
            mhi = fmaxf(mhi, fmaxf(acc[nt][2], acc[nt][3]));
        }
        mlo = fmaxf(mlo, __shfl_xor_sync(FULLM, mlo, 1));
        mlo = fmaxf(mlo, __shfl_xor_sync(FULLM, mlo, 2));
        mhi = fmaxf(mhi, __shfl_xor_sync(FULLM, mhi, 1));
        mhi = fmaxf(mhi, __shfl_xor_sync(FULLM, mhi, 2));
        if ((lane & 3) == 0) {
            int cmi = j * 128 + qq * 64 + cc * 2 + ch;
            g_cm[rowg0 + drow][cmi]     = mlo;
            g_cm[rowg0 + drow + 8][cmi] = mhi;
        }
    }
}

// ---------------------------------------------------------------------------
// Threshold: T[row] = (20th largest of 256 sub-chunk maxima) - DELTA.
// ---------------------------------------------------------------------------
__global__ void thr_kernel() {
    int w = threadIdx.x >> 5, lane = threadIdx.x & 31;
    int row = blockIdx.x * 8 + w;

    float a[8];
#pragma unroll
    for (int s = 0; s < 8; s++) a[s] = g_cm[row][lane + 32 * s];

    float last = -1e30f;
#pragma unroll
    for (int kk = 0; kk < KTOP; kk++) {
        float bv = a[0];
#pragma unroll
        for (int s = 1; s < 8; s++) bv = fmaxf(bv, a[s]);
#pragma unroll
        for (int off = 16; off > 0; off >>= 1)
            bv = fmaxf(bv, __shfl_xor_sync(FULLM, bv, off));
#pragma unroll
        for (int s = 0; s < 8; s++) a[s] = (a[s] == bv) ? -1e30f : a[s];
        last = bv;
    }
    if (lane == 0) g_T[row] = last - DELTA;
}

// ---------------------------------------------------------------------------
// Pass 2: HMMA + filter-append values > T + fused zeroing of the output.
// smem: A+4B(46080) + fv 64*32*4 @46080 + fc @54272 + cnt @58368 = 58624.
// Each CTA zeroes its 512KB slice of out, spread over the chunk loop.
// ---------------------------------------------------------------------------
#define OFF_FV 46080
#define OFF_FC 54272
#define OFF_CN 58368
#define SM2_TOTAL 58624

__global__ void __launch_bounds__(256, 3) score2_kernel(float* __restrict__ out) {
    extern __shared__ char smem[];
    uint32_t sbase = smem_u32(smem);
    int tid = threadIdx.x, wid = tid >> 5, lane = tid & 31;
    int rb = wid & 3, ch = wid >> 2;
    int xq = blockIdx.x, rt = blockIdx.y;
    int j = xq >> 1, qq = xq & 1;
    int mod_i = rt >> 6;
    int k = mod_i * 2 + j;
    int nbase = (rt & 63) * 64;
    int rowg0 = rt * 64;
    int colbase = qq * 2048;

    float* fv = (float*)(smem + OFF_FV);
    unsigned short* fc = (unsigned short*)(smem + OFF_FC);
    int* cnt = (int*)(smem + OFF_CN);
    if (tid < 64) cnt[tid] = 0;

    // this CTA's 512KB zero slice (512 CTAs x 32768 float4 = 256MB)
    float4* ob = (float4*)out + (size_t)(xq * 128 + rt) * 32768;
    const float4 z4 = make_float4(0.f, 0.f, 0.f, 0.f);

    load_A(smem, tid, k, nbase);
    cp_async_B(sbase, tid, k, colbase, 0);
    cp_async_B(sbase, tid, k, colbase, 1);
    cp_async_B(sbase, tid, k, colbase, 2);
    __syncthreads();

    uint32_t af[4][4];
    preload_af(af, sbase, rb, lane);

    int drow = rb * 16 + (lane >> 2);
    int dcol = (lane & 3) * 2;
    float Tlo = g_T[rowg0 + drow];
    float Thi = g_T[rowg0 + drow + 8];
    int cbase = j * 4096 + colbase;

    for (int cc = 0; cc < 32; cc++) {
        asm volatile("cp.async.wait_group 2;");
        __syncthreads();
        if (cc + 3 < 32) cp_async_B(sbase, tid, k, colbase, cc + 3);

        // fused zero: 1024 float4 per chunk (4 per thread), fire-and-forget
        {
            float4* zb = ob + cc * 1024;
#pragma unroll
            for (int f = tid; f < 1024; f += 256) zb[f] = z4;
        }

        uint32_t bbuf = sbase + OFF_B + (cc & 3) * 9216;
        float acc[4][4];
#pragma unroll
        for (int nt = 0; nt < 4; nt++)
#pragma unroll
            for (int s = 0; s < 4; s++) acc[nt][s] = 0.f;
        MMA_CHUNK4(acc, af, bbuf, ch, lane);

#pragma unroll
        for (int nt = 0; nt < 4; nt++) {
            int colb = cbase + cc * 64 + ch * 32 + nt * 8 + dcol;
            if (acc[nt][0] > Tlo) {
                int p = atomicAdd(&cnt[drow], 1);
                if (p < CAND) { fv[drow * CAND + p] = acc[nt][0];
                                fc[drow * CAND + p] = (unsigned short)colb; }
            }
            if (acc[nt][1] > Tlo) {
                int p = atomicAdd(&cnt[drow], 1);
                if (p < CAND) { fv[drow * CAND + p] = acc[nt][1];
                                fc[drow * CAND + p] = (unsigned short)(colb + 1); }
            }
            if (acc[nt][2] > Thi) {
                int p = atomicAdd(&cnt[drow + 8], 1);
                if (p < CAND) { fv[(drow + 8) * CAND + p] = acc[nt][2];
                                fc[(drow + 8) * CAND + p] = (unsigned short)colb; }
            }
            if (acc[nt][3] > Thi) {
                int p = atomicAdd(&cnt[drow + 8], 1);
                if (p < CAND) { fv[(drow + 8) * CAND + p] = acc[nt][3];
                                fc[(drow + 8) * CAND + p] = (unsigned short)(colb + 1); }
            }
        }
    }
    __syncthreads();

    for (int t = tid; t < 64 * CAND; t += 256) {
        int r = t / CAND, i = t % CAND;
        int n = min(cnt[r], CAND);
        g_cval[rowg0 + r][xq * CAND + i] = (i < n) ? fv[t] : -1e30f;
        g_ccol[rowg0 + r][xq * CAND + i] = fc[t];
    }
}

// ---------------------------------------------------------------------------
// Merge: block = 8 rows, warp/row. 128 candidates (4/lane):
// pass-1 bf16 20th -> fp32 rescore of survivors -> pass-2 top-20 -> scatter.
// (output already zeroed by score2)
// ---------------------------------------------------------------------------
__global__ void merge_rescore_kernel(float* __restrict__ out) {
    __shared__ float sv1[8][2][64];
    int tid = threadIdx.x;
    int w = tid >> 5, lane = tid & 31;
    int row = blockIdx.x * 8 + w;
    int mod_i = row >> 12, rloc = row & 4095;

    for (int t = lane; t < 128; t += 32) {
        int h = t >> 6, d = t & 63;
        sv1[w][h][d] = g_v1[mod_i * 2 + h][rloc][d];
    }
    __syncwarp();

    float wv[4]; int col[4];
#pragma unroll
    for (int s = 0; s < 4; s++) {
        int idx = lane * 4 + s;
        wv[s]  = g_cval[row][idx];
        col[s] = (int)g_ccol[row][idx];
    }

    // pass 1: 20th-largest bf16-level candidate (value-only rounds;
    // duplicate clearing lowers thr -> conservative)
    float a0 = wv[0], a1 = wv[1], a2 = wv[2], a3 = wv[3];
    float thr = 0.f;
#pragma unroll
    for (int kk = 0; kk < KTOP; kk++) {
        float bv = fmaxf(fmaxf(a0, a1), fmaxf(a2, a3));
#pragma unroll
        for (int off = 16; off > 0; off >>= 1)
            bv = fmaxf(bv, __shfl_xor_sync(FULLM, bv, off));
        a0 = (a0 == bv) ? -1e30f : a0;
        a1 = (a1 == bv) ? -1e30f : a1;
        a2 = (a2 == bv) ? -1e30f : a2;
        a3 = (a3 == bv) ? -1e30f : a3;
        thr = bv;
    }

    // rescore survivors in exact fp32
    float rv[4];
#pragma unroll
    for (int s = 0; s < 4; s++) {
        if (wv[s] >= thr - DELTA) {
            int h = col[s] >> 12, cl = col[s] & 4095;
            const float4* v2c = (const float4*)&g_v2[mod_i * 2 + h][cl][0];
            const float4* v1c = (const float4*)&sv1[w][h][0];
            float acc = 0.f;
#pragma unroll
            for (int dd = 0; dd < 16; dd++) {
                float4 x = v1c[dd], y = v2c[dd];
                acc += x.x * y.x + x.y * y.y + x.z * y.z + x.w * y.w;
            }
            rv[s] = acc;
        } else {
            rv[s] = -1e30f;
        }
    }

    // pass 2: exact top-20, scatter tanh
#pragma unroll
    for (int kk = 0; kk < KTOP; kk++) {
        float bv = rv[0]; int bs = 0;
        if (rv[1] > bv) { bv = rv[1]; bs = 1; }
        if (rv[2] > bv) { bv = rv[2]; bs = 2; }
        if (rv[3] > bv) { bv = rv[3]; bs = 3; }
        int bc = col[bs];
        int bi = lane * 4 + bs;
#pragma unroll
        for (int off = 16; off > 0; off >>= 1) {
            float ov = __shfl_xor_sync(FULLM, bv, off);
            int   oc = __shfl_xor_sync(FULLM, bc, off);
            int   oi = __shfl_xor_sync(FULLM, bi, off);
            if (ov > bv || (ov == bv && oi < bi)) { bv = ov; bc = oc; bi = oi; }
        }
        if (lane == (bi >> 2)) rv[bi & 3] = -1e30f;
        if (lane == kk) {
            float t = (bv > 0.f) ? tanhf(3.0f * bv) : 0.f;
            out[(size_t)row * NROWS + bc] = t;
        }
    }
}

// ---------------------------------------------------------------------------
extern "C" void kernel_launch(void* const* d_in, const int* in_sizes, int n_in,
                              void* d_out, int out_size) {
    const float* emb1 = (const float*)d_in[1];
    const float* emb2 = (const float*)d_in[2];
    const float* w1   = (const float*)d_in[3];
    const float* w2   = (const float*)d_in[4];
    const float* b1   = (const float*)d_in[5];
    const float* b2   = (const float*)d_in[6];
    float* out = (float*)d_out;

    cudaFuncSetAttribute(score1_kernel,
                         cudaFuncAttributeMaxDynamicSharedMemorySize, SM_AB);
    cudaFuncSetAttribute(score2_kernel,
                         cudaFuncAttributeMaxDynamicSharedMemorySize, SM2_TOTAL);

    compute_v_kernel<<<dim3(64, NMAT, 2), 256>>>(emb1, emb2, w1, w2, b1, b2);
    score1_kernel<<<dim3(4, 128), 256, SM_AB>>>();
    thr_kernel<<<NROWS / 8, 256>>>();
    score2_kernel<<<dim3(4, 128), 256, SM2_TOTAL>>>(out);
    merge_rescore_kernel<<<NROWS / 8, 256>>>(out);
}

// round 16
// speedup vs baseline: 1.1426x; 1.0124x over previous
#include <cuda_runtime.h>
#include <cuda_bf16.h>
#include <math.h>
#include <stdint.h>

#define NMAT 4
#define NSUB 4096
#define DIM 64
#define KTOP 20
#define NROWS 8192
#define DELTA 0.008f
#define FULLM 0xffffffffu
#define CAND 48            // candidates per quarter-row

// device global scratch (no allocation allowed)
__device__ float g_v1[NMAT][NSUB][DIM];
__device__ float g_v2[NMAT][NSUB][DIM];
__device__ __nv_bfloat16 g_v1b[NMAT][NSUB][DIM];
__device__ __nv_bfloat16 g_v2b[NMAT][NSUB][DIM];
__device__ float          g_cm[NROWS][128];       // sampled sub-chunk maxima
__device__ float          g_T[NROWS];             // per-row filter threshold
__device__ float          g_cval[NROWS][4 * CAND];
__device__ unsigned short g_ccol[NROWS][4 * CAND];

__device__ __forceinline__ uint32_t smem_u32(const void* p) {
    uint32_t a;
    asm("{ .reg .u64 t; cvta.to.shared.u64 t, %1; cvt.u32.u64 %0, t; }" : "=r"(a) : "l"(p));
    return a;
}

// ---------------------------------------------------------------------------
// v = emb @ w + b (fp32) + bf16 copy
// ---------------------------------------------------------------------------
__global__ void compute_v_kernel(const float* __restrict__ emb1,
                                 const float* __restrict__ emb2,
                                 const float* __restrict__ w1,
                                 const float* __restrict__ w2,
                                 const float* __restrict__ b1,
                                 const float* __restrict__ b2) {
    int which = blockIdx.z;
    int k = blockIdx.y;
    int tile = blockIdx.x;
    const float* emb = which ? emb2 : emb1;
    const float* w   = which ? w2   : w1;
    const float* b   = which ? b2   : b1;
    float* vout            = which ? &g_v2[0][0][0]  : &g_v1[0][0][0];
    __nv_bfloat16* voutb   = which ? &g_v2b[0][0][0] : &g_v1b[0][0][0];

    __shared__ float semb[64 * 65];
    __shared__ float sw[64 * 64];
    __shared__ float sb[64];

    int tid = threadIdx.x;
    for (int t = tid; t < 4096; t += 256) {
        int r = t >> 6, e = t & 63;
        semb[r * 65 + e] = emb[(size_t)(k * NSUB + tile * 64 + r) * 64 + e];
        sw[t] = w[k * 4096 + t];
    }
    if (tid < 64) sb[tid] = b[k * 64 + tid];
    __syncthreads();

    int nl = tid & 63, q = tid >> 6;
    float acc[16];
#pragma unroll
    for (int d = 0; d < 16; d++) acc[d] = 0.f;

#pragma unroll 4
    for (int e = 0; e < 64; e++) {
        float a = semb[nl * 65 + e];
#pragma unroll
        for (int jj = 0; jj < 4; jj++) {
            float4 wv = *(const float4*)&sw[e * 64 + q * 16 + jj * 4];
            acc[jj * 4 + 0] += a * wv.x;
            acc[jj * 4 + 1] += a * wv.y;
            acc[jj * 4 + 2] += a * wv.z;
            acc[jj * 4 + 3] += a * wv.w;
        }
    }

    size_t rowoff = (size_t)(k * NSUB + tile * 64 + nl) * 64;
    float* orow = vout + rowoff;
    __nv_bfloat16* orowb = voutb + rowoff;
#pragma unroll
    for (int dd = 0; dd < 16; dd++) {
        int d = q * 16 + dd;
        float v = acc[dd] + sb[d];
        orow[d]  = v;
        orowb[d] = __float2bfloat16(v);
    }
}

// ---------------------------------------------------------------------------
// HMMA plumbing. 256 threads, 64-row tiles; warp = (rowband rb = w&3) x
// (colhalf ch = w>>2); warp does 16 rows x 32 cols per 64-col chunk.
// B: 4-stage cp.async ring, 3-deep prefetch. B frags via ldmatrix.x4.
// grid = (xq: 4 [colmodule j = xq>>1, quarter qq = xq&1], rowtile: 128).
// ---------------------------------------------------------------------------
#define OFF_A  0
#define OFF_B  9216
#define SM_AB  46080            // A(9216) + 4 B stages (4x9216)

#define MMA_CHUNK4(acc, af, bbuf, ch, lane)                                     \
    do {                                                                        \
        uint32_t baddr0 = (bbuf) + ((ch) * 32 + ((lane) & 7)) * 144             \
                          + ((lane) >> 3) * 16;                                 \
        _Pragma("unroll")                                                       \
        for (int nt = 0; nt < 4; nt++) {                                        \
            uint32_t ba = baddr0 + nt * 8 * 144;                                \
            uint32_t b0, b1, b2, b3, b4, b5, b6, b7;                            \
            asm volatile("ldmatrix.sync.aligned.m8n8.x4.shared.b16 {%0,%1,%2,%3}, [%4];" \
                         : "=r"(b0), "=r"(b1), "=r"(b2), "=r"(b3) : "r"(ba));   \
            asm volatile("ldmatrix.sync.aligned.m8n8.x4.shared.b16 {%0,%1,%2,%3}, [%4];" \
                         : "=r"(b4), "=r"(b5), "=r"(b6), "=r"(b7) : "r"(ba + 64)); \
            asm volatile("mma.sync.aligned.m16n8k16.row.col.f32.bf16.bf16.f32 " \
                         "{%0,%1,%2,%3}, {%4,%5,%6,%7}, {%8,%9}, {%0,%1,%2,%3};" \
                         : "+f"(acc[nt][0]), "+f"(acc[nt][1]),                  \
                           "+f"(acc[nt][2]), "+f"(acc[nt][3])                   \
                         : "r"(af[0][0]), "r"(af[0][1]), "r"(af[0][2]), "r"(af[0][3]), \
                           "r"(b0), "r"(b1));                                   \
            asm volatile("mma.sync.aligned.m16n8k16.row.col.f32.bf16.bf16.f32 " \
                         "{%0,%1,%2,%3}, {%4,%5,%6,%7}, {%8,%9}, {%0,%1,%2,%3};" \
                         : "+f"(acc[nt][0]), "+f"(acc[nt][1]),                  \
                           "+f"(acc[nt][2]), "+f"(acc[nt][3])                   \
                         : "r"(af[1][0]), "r"(af[1][1]), "r"(af[1][2]), "r"(af[1][3]), \
                           "r"(b2), "r"(b3));                                   \
            asm volatile("mma.sync.aligned.m16n8k16.row.col.f32.bf16.bf16.f32 " \
                         "{%0,%1,%2,%3}, {%4,%5,%6,%7}, {%8,%9}, {%0,%1,%2,%3};" \
                         : "+f"(acc[nt][0]), "+f"(acc[nt][1]),                  \
                           "+f"(acc[nt][2]), "+f"(acc[nt][3])                   \
                         : "r"(af[2][0]), "r"(af[2][1]), "r"(af[2][2]), "r"(af[2][3]), \
                           "r"(b4), "r"(b5));                                   \
            asm volatile("mma.sync.aligned.m16n8k16.row.col.f32.bf16.bf16.f32 " \
                         "{%0,%1,%2,%3}, {%4,%5,%6,%7}, {%8,%9}, {%0,%1,%2,%3};" \
                         : "+f"(acc[nt][0]), "+f"(acc[nt][1]),                  \
                           "+f"(acc[nt][2]), "+f"(acc[nt][3])                   \
                         : "r"(af[3][0]), "r"(af[3][1]), "r"(af[3][2]), "r"(af[3][3]), \
                           "r"(b6), "r"(b7));                                   \
        }                                                                       \
    } while (0)

__device__ __forceinline__ void load_A(char* smem, int tid, int k, int nbase) {
    const int4* asrc = (const int4*)&g_v1b[k][nbase][0];
    for (int f = tid; f < 512; f += 256) {
        int r = f >> 3, q = f & 7;
        *(int4*)(smem + OFF_A + r * 144 + q * 16) = asrc[f];
    }
}

// 8KB B chunk (64 rows starting at row0): slot = ring slot 0..3
__device__ __forceinline__ void cp_async_B(uint32_t sbase, int tid, int k,
                                           int row0, int slot) {
    const int4* src = (const int4*)&g_v2b[k][row0][0];
#pragma unroll
    for (int f = tid; f < 512; f += 256) {
        int r = f >> 3, q = f & 7;
        uint32_t dst = sbase + OFF_B + slot * 9216 + r * 144 + q * 16;
        asm volatile("cp.async.cg.shared.global [%0], [%1], 16;" :: "r"(dst), "l"(src + f));
    }
    asm volatile("cp.async.commit_group;");
}

__device__ __forceinline__ void preload_af(uint32_t af[4][4], uint32_t sbase, int rb, int lane) {
    uint32_t abase = sbase + OFF_A + (rb * 16 + (lane & 15)) * 144 + (lane >> 4) * 16;
#pragma unroll
    for (int ks = 0; ks < 4; ks++) {
        asm volatile("ldmatrix.sync.aligned.m8n8.x4.shared.b16 {%0,%1,%2,%3}, [%4];"
                     : "=r"(af[ks][0]), "=r"(af[ks][1]), "=r"(af[ks][2]), "=r"(af[ks][3])
                     : "r"(abase + ks * 32));
    }
}

// ---------------------------------------------------------------------------
// Pass 1: HMMA over EVEN 64-col chunks only (half sample) + sub-chunk maxima
// + zero first half of this CTA's output slice.
// ---------------------------------------------------------------------------
__global__ void __launch_bounds__(256, 3) score1_kernel(float* __restrict__ out) {
    extern __shared__ char smem[];
    uint32_t sbase = smem_u32(smem);
    int tid = threadIdx.x, wid = tid >> 5, lane = tid & 31;
    int rb = wid & 3, ch = wid >> 2;
    int xq = blockIdx.x, rt = blockIdx.y;
    int j = xq >> 1, qq = xq & 1;
    int mod_i = rt >> 6;
    int k = mod_i * 2 + j;
    int nbase = (rt & 63) * 64;
    int rowg0 = rt * 64;
    int colbase = qq * 2048;
    int q4 = j * 2 + qq;

    // zero slice: first 256KB of this CTA's 512KB share (16384 float4)
    float4* ob = (float4*)out + (size_t)(xq * 128 + rt) * 32768;
    const float4 z4 = make_float4(0.f, 0.f, 0.f, 0.f);

    load_A(smem, tid, k, nbase);
    cp_async_B(sbase, tid, k, colbase + 0 * 128, 0);
    cp_async_B(sbase, tid, k, colbase + 1 * 128, 1);
    cp_async_B(sbase, tid, k, colbase + 2 * 128, 2);
    __syncthreads();

    uint32_t af[4][4];
    preload_af(af, sbase, rb, lane);

    int drow = rb * 16 + (lane >> 2);

    for (int cc = 0; cc < 16; cc++) {       // sampled chunk = column 128*cc
        asm volatile("cp.async.wait_group 2;");
        __syncthreads();
        if (cc + 3 < 16) cp_async_B(sbase, tid, k, colbase + (cc + 3) * 128, (cc + 3) & 3);

        // fused zero: 1024 float4 per iter (4/thread)
        {
            float4* zb = ob + cc * 1024;
#pragma unroll
            for (int f = tid; f < 1024; f += 256) zb[f] = z4;
        }

        uint32_t bbuf = sbase + OFF_B + (cc & 3) * 9216;
        float acc[4][4];
#pragma unroll
        for (int nt = 0; nt < 4; nt++)
#pragma unroll
            for (int s = 0; s < 4; s++) acc[nt][s] = 0.f;
        MMA_CHUNK4(acc, af, bbuf, ch, lane);

        float mlo = acc[0][0], mhi = acc[0][2];
#pragma unroll
        for (int nt = 0; nt < 4; nt++) {
            mlo = fmaxf(mlo, fmaxf(acc[nt][0], acc[nt][1]));
            mhi = fmaxf(mhi, fmaxf(acc[nt][2], acc[nt][3]));
        }
        mlo = fmaxf(mlo, __shfl_xor_sync(FULLM, mlo, 1));
        mlo = fmaxf(mlo, __shfl_xor_sync(FULLM, mlo, 2));
        mhi = fmaxf(mhi, __shfl_xor_sync(FULLM, mhi, 1));
        mhi = fmaxf(mhi, __shfl_xor_sync(FULLM, mhi, 2));
        if ((lane & 3) == 0) {
            int cmi = q4 * 32 + cc * 2 + ch;
            g_cm[rowg0 + drow][cmi]     = mlo;
            g_cm[rowg0 + drow + 8][cmi] = mhi;
        }
    }
}

// ---------------------------------------------------------------------------
// Threshold: T[row] = (20th largest of 128 sampled maxima) - DELTA.
// (Sampled maxima are actual row scores -> 20th-largest <= v20: valid.)
// ---------------------------------------------------------------------------
__global__ void thr_kernel() {
    int w = threadIdx.x >> 5, lane = threadIdx.x & 31;
    int row = blockIdx.x * 8 + w;

    float a[4];
#pragma unroll
    for (int s = 0; s < 4; s++) a[s] = g_cm[row][lane + 32 * s];

    float last = -1e30f;
#pragma unroll
    for (int kk = 0; kk < KTOP; kk++) {
        float bv = fmaxf(fmaxf(a[0], a[1]), fmaxf(a[2], a[3]));
#pragma unroll
        for (int off = 16; off > 0; off >>= 1)
            bv = fmaxf(bv, __shfl_xor_sync(FULLM, bv, off));
#pragma unroll
        for (int s = 0; s < 4; s++) a[s] = (a[s] == bv) ? -1e30f : a[s];
        last = bv;
    }
    if (lane == 0) g_T[row] = last - DELTA;
}

// ---------------------------------------------------------------------------
// Pass 2: HMMA all 32 chunks + filter-append values > T + zero second half.
// smem: A+4B(46080) + fv 64*48*4 @46080 + fc @58368 + cnt @64512 = 64768.
// ---------------------------------------------------------------------------
#define OFF_FV 46080
#define OFF_FC 58368
#define OFF_CN 64512
#define SM2_TOTAL 64768

__global__ void __launch_bounds__(256, 3) score2_kernel(float* __restrict__ out) {
    extern __shared__ char smem[];
    uint32_t sbase = smem_u32(smem);
    int tid = threadIdx.x, wid = tid >> 5, lane = tid & 31;
    int rb = wid & 3, ch = wid >> 2;
    int xq = blockIdx.x, rt = blockIdx.y;
    int j = xq >> 1, qq = xq & 1;
    int mod_i = rt >> 6;
    int k = mod_i * 2 + j;
    int nbase = (rt & 63) * 64;
    int rowg0 = rt * 64;
    int colbase = qq * 2048;

    float* fv = (float*)(smem + OFF_FV);
    unsigned short* fc = (unsigned short*)(smem + OFF_FC);
    int* cnt = (int*)(smem + OFF_CN);
    if (tid < 64) cnt[tid] = 0;

    // zero slice: second 256KB of this CTA's 512KB share
    float4* ob = (float4*)out + (size_t)(xq * 128 + rt) * 32768 + 16384;
    const float4 z4 = make_float4(0.f, 0.f, 0.f, 0.f);

    load_A(smem, tid, k, nbase);
    cp_async_B(sbase, tid, k, colbase + 0 * 64, 0);
    cp_async_B(sbase, tid, k, colbase + 1 * 64, 1);
    cp_async_B(sbase, tid, k, colbase + 2 * 64, 2);
    __syncthreads();

    uint32_t af[4][4];
    preload_af(af, sbase, rb, lane);

    int drow = rb * 16 + (lane >> 2);
    int dcol = (lane & 3) * 2;
    float Tlo = g_T[rowg0 + drow];
    float Thi = g_T[rowg0 + drow + 8];
    int cbase = j * 4096 + colbase;

    for (int cc = 0; cc < 32; cc++) {
        asm volatile("cp.async.wait_group 2;");
        __syncthreads();
        if (cc + 3 < 32) cp_async_B(sbase, tid, k, colbase + (cc + 3) * 64, (cc + 3) & 3);

        // fused zero: 512 float4 per chunk (2/thread)
        {
            float4* zb = ob + cc * 512;
#pragma unroll
            for (int f = tid; f < 512; f += 256) zb[f] = z4;
        }

        uint32_t bbuf = sbase + OFF_B + (cc & 3) * 9216;
        float acc[4][4];
#pragma unroll
        for (int nt = 0; nt < 4; nt++)
#pragma unroll
            for (int s = 0; s < 4; s++) acc[nt][s] = 0.f;
        MMA_CHUNK4(acc, af, bbuf, ch, lane);

#pragma unroll
        for (int nt = 0; nt < 4; nt++) {
            int colb = cbase + cc * 64 + ch * 32 + nt * 8 + dcol;
            if (acc[nt][0] > Tlo) {
                int p = atomicAdd(&cnt[drow], 1);
                if (p < CAND) { fv[drow * CAND + p] = acc[nt][0];
                                fc[drow * CAND + p] = (unsigned short)colb; }
            }
            if (acc[nt][1] > Tlo) {
                int p = atomicAdd(&cnt[drow], 1);
                if (p < CAND) { fv[drow * CAND + p] = acc[nt][1];
                                fc[drow * CAND + p] = (unsigned short)(colb + 1); }
            }
            if (acc[nt][2] > Thi) {
                int p = atomicAdd(&cnt[drow + 8], 1);
                if (p < CAND) { fv[(drow + 8) * CAND + p] = acc[nt][2];
                                fc[(drow + 8) * CAND + p] = (unsigned short)colb; }
            }
            if (acc[nt][3] > Thi) {
                int p = atomicAdd(&cnt[drow + 8], 1);
                if (p < CAND) { fv[(drow + 8) * CAND + p] = acc[nt][3];
                                fc[(drow + 8) * CAND + p] = (unsigned short)(colb + 1); }
            }
        }
    }
    __syncthreads();

    for (int t = tid; t < 64 * CAND; t += 256) {
        int r = t / CAND, i = t % CAND;
        int n = min(cnt[r], CAND);
        g_cval[rowg0 + r][xq * CAND + i] = (i < n) ? fv[t] : -1e30f;
        g_ccol[rowg0 + r][xq * CAND + i] = fc[t];
    }
}

// ---------------------------------------------------------------------------
// Merge: block = 8 rows, warp/row. 192 candidates (6/lane):
// pass-1 bf16 20th -> fp32 rescore of survivors -> pass-2 top-20 -> scatter.
// (output already zeroed by score1 + score2)
// ---------------------------------------------------------------------------
__global__ void merge_rescore_kernel(float* __restrict__ out) {
    __shared__ float sv1[8][2][64];
    int tid = threadIdx.x;
    int w = tid >> 5, lane = tid & 31;
    int row = blockIdx.x * 8 + w;
    int mod_i = row >> 12, rloc = row & 4095;

    for (int t = lane; t < 128; t += 32) {
        int h = t >> 6, d = t & 63;
        sv1[w][h][d] = g_v1[mod_i * 2 + h][rloc][d];
    }
    __syncwarp();

    float wv[6]; int col[6];
#pragma unroll
    for (int s = 0; s < 6; s++) {
        int idx = lane * 6 + s;
        wv[s]  = g_cval[row][idx];
        col[s] = (int)g_ccol[row][idx];
    }

    // pass 1: 20th-largest bf16-level candidate (value-only rounds;
    // duplicate clearing lowers thr -> conservative)
    float a0 = wv[0], a1 = wv[1], a2 = wv[2], a3 = wv[3], a4 = wv[4], a5 = wv[5];
    float thr = 0.f;
#pragma unroll
    for (int kk = 0; kk < KTOP; kk++) {
        float bv = fmaxf(fmaxf(fmaxf(a0, a1), fmaxf(a2, a3)), fmaxf(a4, a5));
#pragma unroll
        for (int off = 16; off > 0; off >>= 1)
            bv = fmaxf(bv, __shfl_xor_sync(FULLM, bv, off));
        a0 = (a0 == bv) ? -1e30f : a0;
        a1 = (a1 == bv) ? -1e30f : a1;
        a2 = (a2 == bv) ? -1e30f : a2;
        a3 = (a3 == bv) ? -1e30f : a3;
        a4 = (a4 == bv) ? -1e30f : a4;
        a5 = (a5 == bv) ? -1e30f : a5;
        thr = bv;
    }

    // rescore survivors in exact fp32
    float rv[6];
#pragma unroll
    for (int s = 0; s < 6; s++) {
        if (wv[s] >= thr - DELTA) {
            int h = col[s] >> 12, cl = col[s] & 4095;
            const float4* v2c = (const float4*)&g_v2[mod_i * 2 + h][cl][0];
            const float4* v1c = (const float4*)&sv1[w][h][0];
            float acc = 0.f;
#pragma unroll
            for (int dd = 0; dd < 16; dd++) {
                float4 x = v1c[dd], y = v2c[dd];
                acc += x.x * y.x + x.y * y.y + x.z * y.z + x.w * y.w;
            }
            rv[s] = acc;
        } else {
            rv[s] = -1e30f;
        }
    }

    // pass 2: exact top-20, scatter tanh
#pragma unroll
    for (int kk = 0; kk < KTOP; kk++) {
        float bv = rv[0]; int bs = 0;
        if (rv[1] > bv) { bv = rv[1]; bs = 1; }
        if (rv[2] > bv) { bv = rv[2]; bs = 2; }
        if (rv[3] > bv) { bv = rv[3]; bs = 3; }
        if (rv[4] > bv) { bv = rv[4]; bs = 4; }
        if (rv[5] > bv) { bv = rv[5]; bs = 5; }
        int bc = col[bs];
        int bi = lane * 8 + bs;
#pragma unroll
        for (int off = 16; off > 0; off >>= 1) {
            float ov = __shfl_xor_sync(FULLM, bv, off);
            int   oc = __shfl_xor_sync(FULLM, bc, off);
            int   oi = __shfl_xor_sync(FULLM, bi, off);
            if (ov > bv || (ov == bv && oi < bi)) { bv = ov; bc = oc; bi = oi; }
        }
        if (lane == (bi >> 3)) rv[bi & 7] = -1e30f;
        if (lane == kk) {
            float t = (bv > 0.f) ? tanhf(3.0f * bv) : 0.f;
            out[(size_t)row * NROWS + bc] = t;
        }
    }
}

// ---------------------------------------------------------------------------
extern "C" void kernel_launch(void* const* d_in, const int* in_sizes, int n_in,
                              void* d_out, int out_size) {
    const float* emb1 = (const float*)d_in[1];
    const float* emb2 = (const float*)d_in[2];
    const float* w1   = (const float*)d_in[3];
    const float* w2   = (const float*)d_in[4];
    const float* b1   = (const float*)d_in[5];
    const float* b2   = (const float*)d_in[6];
    float* out = (float*)d_out;

    cudaFuncSetAttribute(score1_kernel,
                         cudaFuncAttributeMaxDynamicSharedMemorySize, SM_AB);
    cudaFuncSetAttribute(score2_kernel,
                         cudaFuncAttributeMaxDynamicSharedMemorySize, SM2_TOTAL);

    compute_v_kernel<<<dim3(64, NMAT, 2), 256>>>(emb1, emb2, w1, w2, b1, b2);
    score1_kernel<<<dim3(4, 128), 256, SM_AB>>>(out);
    thr_kernel<<<NROWS / 8, 256>>>();
    score2_kernel<<<dim3(4, 128), 256, SM2_TOTAL>>>(out);
    merge_rescore_kernel<<<NROWS / 8, 256>>>(out);
}